// round 4
// baseline (speedup 1.0000x reference)
#include <cuda_runtime.h>
#include <math.h>
#include <stdint.h>

#define D_NODE 100
#define D_EDGE 172
#define D_TIME 100
#define NKV    372
#define DOUT   100
#define EMAX   320000
#define DMAX   20000
#define MINN   1e-15f
#define MAXN   0.996f
#define SLOPE  0.2f

__device__ float    g_Qd[DMAX * DOUT];
__device__ float    g_dsthyp[DMAX * D_NODE];
__device__ float    g_V[(size_t)EMAX * DOUT];
__device__ float    g_scores[EMAX * 2];
__device__ float    g_ez[EMAX * 2];
__device__ unsigned g_smax[DMAX * 2];
__device__ float    g_ssum[DMAX * 2];
__device__ float    g_hagg[DMAX * DOUT];
__device__ float    g_hb[4 * DOUT];
__device__ float    g_hb2[4];
__device__ float    g_ztf[D_TIME];
__device__ float    g_ztf_e2;

__device__ __forceinline__ float wsum32(float v) {
#pragma unroll
    for (int m = 16; m; m >>= 1) v += __shfl_xor_sync(0xffffffffu, v, m);
    return v;
}
__device__ __forceinline__ float wsum16(float v) {
#pragma unroll
    for (int m = 8; m; m >>= 1) v += __shfl_xor_sync(0xffffffffu, v, m);
    return v;
}
__device__ __forceinline__ float artanh_f(float x) {
    x = fminf(fmaxf(x, -1.0f + 1e-7f), 1.0f - 1e-7f);
    return 0.5f * (log1pf(x) - log1pf(-x));
}
// hyp_encode = proj(expmap0(u)): pure scale s; en = resulting norm
__device__ __forceinline__ void enc_scale(float ss, float& s, float& en) {
    float n = sqrtf(ss), nn = fmaxf(n, MINN);
    float t = tanhf(nn);
    en = fminf(t, MAXN);
    s = en / nn;
}
// hyp_linear epilogue scalars: out = alpha*mx + beta*hb ; nprev = ||out||
__device__ __forceinline__ void hyp_ab(float mxn2, float xn, float dot_mh, float hb2,
                                       float& alpha, float& beta, float& nprev) {
    float mxn = fmaxf(sqrtf(mxn2), MINN);
    float t = tanhf(mxn / xn * artanh_f(xn));
    float nres = fminf(t, MAXN);
    float s1 = nres / mxn;
    float x2 = nres * nres;
    float xy = s1 * dot_mh;
    float a = 1.f + 2.f * xy + hb2;
    float bb = 1.f - x2;
    float den = fmaxf(1.f + 2.f * xy + x2 * hb2, MINN);
    float n2 = fmaxf(a * a * x2 + 2.f * a * bb * xy + bb * bb * hb2, 0.f);
    float nout = sqrtf(n2) / den;
    float ps = nout > MAXN ? MAXN / nout : 1.f;
    alpha = ps * a * s1 / den;
    beta = ps * bb / den;
    nprev = fminf(nout, MAXN);
}
__device__ __forceinline__ unsigned fenc(float f) {
    unsigned b = __float_as_uint(f);
    return (b & 0x80000000u) ? ~b : (b | 0x80000000u);
}
__device__ __forceinline__ float fdec(unsigned u) {
    return __uint_as_float((u & 0x80000000u) ? (u & 0x7fffffffu) : ~u);
}
__device__ __forceinline__ float lrelu(float x) { return x > 0.f ? x : SLOPE * x; }

// ---------------- init: hb vectors, ztf, zero accumulators -------------------
__global__ void k_init(const float* __restrict__ bq, const float* __restrict__ bk,
                       const float* __restrict__ bv, const float* __restrict__ bo,
                       const float* __restrict__ tb, int D) {
    int tid = blockIdx.x * blockDim.x + threadIdx.x;
    int nt = gridDim.x * blockDim.x;
    for (int i = tid; i < D * DOUT; i += nt) g_hagg[i] = 0.f;
    for (int i = tid; i < 2 * D; i += nt) { g_ssum[i] = 0.f; g_smax[i] = 0u; }
    if (blockIdx.x == 0) {
        int w = threadIdx.x >> 5, l = threadIdx.x & 31;
        if (w < 5) {
            const float* bp = (w == 0) ? bq : (w == 1) ? bk : (w == 2) ? bv : (w == 3) ? bo : tb;
            float v[4]; float ss = 0.f;
#pragma unroll
            for (int m = 0; m < 4; ++m) {
                int o = l + 32 * m;
                float x = (o < DOUT) ? bp[o] : 0.f;
                if (w == 4) x = cosf(x);
                v[m] = (o < DOUT) ? x : 0.f;
                ss += v[m] * v[m];
            }
            ss = wsum32(ss);
            float s, en; enc_scale(ss, s, en);
#pragma unroll
            for (int m = 0; m < 4; ++m) {
                int o = l + 32 * m;
                if (o < DOUT) { if (w < 4) g_hb[w * DOUT + o] = v[m] * s; else g_ztf[o] = v[m] * s; }
            }
            if (l == 0) { if (w < 4) g_hb2[w] = en * en; else g_ztf_e2 = en * en; }
        }
    }
}

// ---------------- k1: per-dst encode + Q projection (200 -> 100) -------------
__global__ void __launch_bounds__(256) k1_dst(const float* __restrict__ dst_h,
                                              const float* __restrict__ Wq, int D) {
    extern __shared__ float sm[];
    float* Ws = sm;               // [200][133] -> reused as M [32][104]
    float* Xs = sm + 200 * 133;   // [32][200]
    __shared__ float s_xn[32];
    int t = threadIdx.x, w = t >> 5, l = t & 31;
    int rbase = blockIdx.x * 32;
    float ztf_e2 = g_ztf_e2;
    for (int i = 0; i < 4; ++i) {
        int r = w * 4 + i, gr = rbase + r;
        float* xr = Xs + r * 200;
        if (gr < D) {
            const float* dr = dst_h + (size_t)gr * D_NODE;
            float v[4]; float ss = 0.f;
#pragma unroll
            for (int m = 0; m < 4; ++m) { int o = l + 32 * m; v[m] = (o < 100) ? dr[o] : 0.f; ss += v[m] * v[m]; }
            ss = wsum32(ss);
            float s, en; enc_scale(ss, s, en);
#pragma unroll
            for (int m = 0; m < 4; ++m) {
                int o = l + 32 * m;
                if (o < 100) {
                    float h = v[m] * s;
                    xr[o] = h; xr[100 + o] = g_ztf[o];
                    g_dsthyp[(size_t)gr * 100 + o] = h;
                }
            }
            if (l == 0) s_xn[r] = fmaxf(sqrtf(en * en + ztf_e2), MINN);
        } else {
            for (int o = l; o < 200; o += 32) xr[o] = 0.f;
            if (l == 0) s_xn[r] = MINN;
        }
    }
    for (int i = t; i < 28 * 200; i += 256) { int o = 100 + i / 200, k = i % 200; Ws[k * 133 + o] = 0.f; }
    for (int i = t; i < 100 * 200; i += 256) { int o = i / 200, k = i % 200; Ws[k * 133 + o] = Wq[i]; }
    __syncthreads();
    int oc = t & 127, g = t >> 7;
    float acc[16];
#pragma unroll
    for (int rr = 0; rr < 16; ++rr) acc[rr] = 0.f;
    for (int k = 0; k < 200; ++k) {
        float wv = Ws[k * 133 + oc];
#pragma unroll
        for (int rr = 0; rr < 16; ++rr) acc[rr] = fmaf(Xs[(g * 16 + rr) * 200 + k], wv, acc[rr]);
    }
    __syncthreads();
    float* Ms = Ws;
    if (oc < 100) {
#pragma unroll
        for (int rr = 0; rr < 16; ++rr) Ms[(g * 16 + rr) * 104 + oc] = acc[rr];
    }
    __syncthreads();
    float hb2 = g_hb2[0];
    for (int i = 0; i < 4; ++i) {
        int r = w * 4 + i, gr = rbase + r;
        if (gr >= D) continue;
        float mv[4], hv[4]; float pn = 0.f, pd = 0.f;
#pragma unroll
        for (int m = 0; m < 4; ++m) {
            int o = l + 32 * m;
            float a = (o < 100) ? Ms[r * 104 + o] : 0.f;
            float h = (o < 100) ? g_hb[o] : 0.f;
            mv[m] = a; hv[m] = h; pn += a * a; pd += a * h;
        }
        pn = wsum32(pn); pd = wsum32(pd);
        float alpha, beta, np;
        hyp_ab(pn, s_xn[r], pd, hb2, alpha, beta, np);
#pragma unroll
        for (int m = 0; m < 4; ++m) {
            int o = l + 32 * m;
            if (o < 100) g_Qd[(size_t)gr * 100 + o] = alpha * mv[m] + beta * hv[m];
        }
    }
}

// ---------------- k2: fused edge encode + K/V GEMMs + scores -----------------
#define TE   64
#define KC   124
#define XPAD 380
__global__ void __launch_bounds__(256) k2_edge(
    const float* __restrict__ neigh, const float* __restrict__ edgef,
    const float* __restrict__ dtp, const int* __restrict__ edst,
    const float* __restrict__ Wk, const float* __restrict__ Wv,
    const float* __restrict__ tw, const float* __restrict__ tb, int E) {
    extern __shared__ float sm[];
    float* Xs = sm;              // [64][380]
    float* Ws = sm + TE * XPAD;  // [124][132] -> reused as Kt [64][104]
    __shared__ float s_xn[TE];
    __shared__ int s_dst[TE];
    __shared__ float s_hb[DOUT];
    __shared__ float s_hb2;
    int t = threadIdx.x, w = t >> 5, l = t & 31;
    int base = blockIdx.x * TE;

    for (int i = 0; i < 8; ++i) {
        int e = w * 8 + i, ge = base + e;
        float* xr = Xs + e * XPAD;
        if (ge < E) {
            float ss, s, e1, e2, e3;
            const float* nr = neigh + (size_t)ge * D_NODE;
            float v[4]; ss = 0.f;
#pragma unroll
            for (int m = 0; m < 4; ++m) { int o = l + 32 * m; v[m] = (o < 100) ? nr[o] : 0.f; ss += v[m] * v[m]; }
            ss = wsum32(ss); enc_scale(ss, s, e1);
#pragma unroll
            for (int m = 0; m < 4; ++m) { int o = l + 32 * m; if (o < 100) xr[o] = v[m] * s; }
            const float* er2 = edgef + (size_t)ge * D_EDGE;
            float u[6]; ss = 0.f;
#pragma unroll
            for (int m = 0; m < 6; ++m) { int o = l + 32 * m; u[m] = (o < 172) ? er2[o] : 0.f; ss += u[m] * u[m]; }
            ss = wsum32(ss); enc_scale(ss, s, e2);
#pragma unroll
            for (int m = 0; m < 6; ++m) { int o = l + 32 * m; if (o < 172) xr[100 + o] = u[m] * s; }
            float dtv = dtp[ge];
            float cc[4]; ss = 0.f;
#pragma unroll
            for (int m = 0; m < 4; ++m) {
                int o = l + 32 * m;
                float c = (o < 100) ? cosf(fmaf(dtv, tw[o], tb[o])) : 0.f;
                cc[m] = c; ss += c * c;
            }
            ss = wsum32(ss); enc_scale(ss, s, e3);
#pragma unroll
            for (int m = 0; m < 4; ++m) { int o = l + 32 * m; if (o < 100) xr[272 + o] = cc[m] * s; }
            if (l == 0) { s_xn[e] = fmaxf(sqrtf(e1 * e1 + e2 * e2 + e3 * e3), MINN); s_dst[e] = edst[ge]; }
        } else {
            for (int o = l; o < NKV; o += 32) xr[o] = 0.f;
            if (l == 0) { s_xn[e] = MINN; s_dst[e] = 0; }
        }
    }

    int er = (t >> 4) * 4, oc = (t & 15) * 8;
    float acc[4][8], alpha[4], beta[4];

    for (int pass = 0; pass < 2; ++pass) {
        const float* Wm = pass ? Wv : Wk;
        int hbi = pass ? 2 : 1;
        __syncthreads();
        for (int i = t; i < 28 * KC; i += 256) { int o = 100 + i / KC, kk = i % KC; Ws[kk * 132 + o] = 0.f; }
        for (int o = t; o < DOUT; o += 256) s_hb[o] = g_hb[hbi * DOUT + o];
        if (t == 0) s_hb2 = g_hb2[hbi];
#pragma unroll
        for (int i2 = 0; i2 < 4; ++i2)
#pragma unroll
            for (int j = 0; j < 8; ++j) acc[i2][j] = 0.f;
        for (int kc = 0; kc < NKV; kc += KC) {
            __syncthreads();
            for (int i = t; i < 100 * KC; i += 256) {
                int o = i / KC, kk = i % KC;
                Ws[kk * 132 + o] = Wm[o * NKV + kc + kk];
            }
            __syncthreads();
            for (int kk = 0; kk < KC; ++kk) {
                float wv[8];
#pragma unroll
                for (int j = 0; j < 8; ++j) wv[j] = Ws[kk * 132 + oc + j];
#pragma unroll
                for (int i2 = 0; i2 < 4; ++i2) {
                    float xv = Xs[(er + i2) * XPAD + kc + kk];
#pragma unroll
                    for (int j = 0; j < 8; ++j) acc[i2][j] = fmaf(xv, wv[j], acc[i2][j]);
                }
            }
        }
        float hb2 = s_hb2;
#pragma unroll
        for (int i2 = 0; i2 < 4; ++i2) {
            float pn = 0.f, pd = 0.f;
#pragma unroll
            for (int j = 0; j < 8; ++j) {
                float a = acc[i2][j];
                pn += a * a;
                int o = oc + j;
                if (o < DOUT) pd += a * s_hb[o];
            }
            pn = wsum16(pn); pd = wsum16(pd);
            float np;
            hyp_ab(pn, s_xn[er + i2], pd, hb2, alpha[i2], beta[i2], np);
        }
        if (pass == 0) {
            __syncthreads();
            float* Kt = Ws;
#pragma unroll
            for (int i2 = 0; i2 < 4; ++i2)
#pragma unroll
                for (int j = 0; j < 8; ++j) {
                    int o = oc + j;
                    if (o < DOUT) Kt[(er + i2) * 104 + o] = alpha[i2] * acc[i2][j] + beta[i2] * s_hb[o];
                }
            __syncthreads();
            for (int i = 0; i < 8; ++i) {
                int e = w * 8 + i, ge = base + e;
                if (ge >= E) continue;
                int dv = s_dst[e];
                const float* q = g_Qd + (size_t)dv * DOUT;
                float s0 = 0.f, s1v = 0.f;
                for (int o = l; o < DOUT; o += 32) {
                    float p = q[o] * Kt[e * 104 + o];
                    if (o < 50) s0 += p; else s1v += p;
                }
                s0 = wsum32(s0); s1v = wsum32(s1v);
                if (l == 0) {
                    float r0 = lrelu(s0), r1 = lrelu(s1v);
                    g_scores[2 * ge] = r0; g_scores[2 * ge + 1] = r1;
                    atomicMax(&g_smax[2 * dv], fenc(r0));
                    atomicMax(&g_smax[2 * dv + 1], fenc(r1));
                }
            }
        } else {
#pragma unroll
            for (int i2 = 0; i2 < 4; ++i2) {
                int ge = base + er + i2;
                if (ge >= E) continue;
#pragma unroll
                for (int j = 0; j < 8; ++j) {
                    int o = oc + j;
                    if (o < DOUT) g_V[(size_t)ge * DOUT + o] = alpha[i2] * acc[i2][j] + beta[i2] * s_hb[o];
                }
            }
        }
    }
}

// ---------------- k3: exp + segment sum --------------------------------------
__global__ void k3_exp(const int* __restrict__ edst, int E) {
    int e = blockIdx.x * blockDim.x + threadIdx.x;
    if (e >= E) return;
    int d = edst[e];
    float z0 = expf(g_scores[2 * e] - fdec(g_smax[2 * d]));
    float z1 = expf(g_scores[2 * e + 1] - fdec(g_smax[2 * d + 1]));
    g_ez[2 * e] = z0; g_ez[2 * e + 1] = z1;
    atomicAdd(&g_ssum[2 * d], z0);
    atomicAdd(&g_ssum[2 * d + 1], z1);
}

// ---------------- k4: weighted scatter aggregate -----------------------------
__global__ void k4_agg(const int* __restrict__ edst, int E) {
    int gw = (blockIdx.x * blockDim.x + threadIdx.x) >> 5;
    int l = threadIdx.x & 31;
    if (gw >= E) return;
    int d = edst[gw];
    float a0 = g_ez[2 * gw] / fmaxf(g_ssum[2 * d], MINN);
    float a1 = g_ez[2 * gw + 1] / fmaxf(g_ssum[2 * d + 1], MINN);
    const float* vr = g_V + (size_t)gw * DOUT;
    float* hr = g_hagg + (size_t)d * DOUT;
    for (int o = l; o < DOUT; o += 32) atomicAdd(&hr[o], vr[o] * (o < 50 ? a0 : a1));
}

// ---------------- k5: O projection + HypAct + logmap0 + LayerNorm ------------
__global__ void __launch_bounds__(256) k5_final(const float* __restrict__ Wo,
                                                const float* __restrict__ lng,
                                                const float* __restrict__ lnb,
                                                float* __restrict__ out, int D) {
    extern __shared__ float sm[];
    float* Ws = sm;
    float* Xs = sm + 200 * 133;
    __shared__ float s_xn[32];
    int t = threadIdx.x, w = t >> 5, l = t & 31;
    int rbase = blockIdx.x * 32;
    for (int i = 0; i < 4; ++i) {
        int r = w * 4 + i, gr = rbase + r;
        float* xr = Xs + r * 200;
        if (gr < D) {
            const float* ha = g_hagg + (size_t)gr * DOUT;
            const float* dh = g_dsthyp + (size_t)gr * D_NODE;
            float ss = 0.f;
#pragma unroll
            for (int m = 0; m < 4; ++m) {
                int o = l + 32 * m;
                float a = (o < 100) ? ha[o] : 0.f;
                float b = (o < 100) ? dh[o] : 0.f;
                if (o < 100) { xr[o] = a; xr[100 + o] = b; }
                ss += a * a + b * b;
            }
            ss = wsum32(ss);
            if (l == 0) s_xn[r] = fmaxf(sqrtf(ss), MINN);
        } else {
            for (int o = l; o < 200; o += 32) xr[o] = 0.f;
            if (l == 0) s_xn[r] = MINN;
        }
    }
    for (int i = t; i < 28 * 200; i += 256) { int o = 100 + i / 200, k = i % 200; Ws[k * 133 + o] = 0.f; }
    for (int i = t; i < 100 * 200; i += 256) { int o = i / 200, k = i % 200; Ws[k * 133 + o] = Wo[i]; }
    __syncthreads();
    int oc = t & 127, g = t >> 7;
    float acc[16];
#pragma unroll
    for (int rr = 0; rr < 16; ++rr) acc[rr] = 0.f;
    for (int k = 0; k < 200; ++k) {
        float wv = Ws[k * 133 + oc];
#pragma unroll
        for (int rr = 0; rr < 16; ++rr) acc[rr] = fmaf(Xs[(g * 16 + rr) * 200 + k], wv, acc[rr]);
    }
    __syncthreads();
    float* Ms = Ws;
    if (oc < 100) {
#pragma unroll
        for (int rr = 0; rr < 16; ++rr) Ms[(g * 16 + rr) * 104 + oc] = acc[rr];
    }
    __syncthreads();
    float hb2 = g_hb2[3];
    for (int i = 0; i < 4; ++i) {
        int r = w * 4 + i, gr = rbase + r;
        if (gr >= D) continue;
        float mv[4], hv[4]; float pn = 0.f, pd = 0.f;
#pragma unroll
        for (int m = 0; m < 4; ++m) {
            int o = l + 32 * m;
            float a = (o < 100) ? Ms[r * 104 + o] : 0.f;
            float h = (o < 100) ? g_hb[3 * DOUT + o] : 0.f;
            mv[m] = a; hv[m] = h; pn += a * a; pd += a * h;
        }
        pn = wsum32(pn); pd = wsum32(pd);
        float alpha, beta, nprev;
        hyp_ab(pn, s_xn[r], pd, hb2, alpha, beta, nprev);
        float lc = artanh_f(nprev) / fmaxf(nprev, MINN);
        float u2v[4]; float uss = 0.f;
#pragma unroll
        for (int m = 0; m < 4; ++m) {
            float u2 = lrelu(lc * (alpha * mv[m] + beta * hv[m]));
            u2v[m] = u2; uss += u2 * u2;
        }
        uss = wsum32(uss);
        float s2, en3; enc_scale(uss, s2, en3);
        float hsc = artanh_f(en3) / fmaxf(en3, MINN) * s2;
        float hvv[4]; float hs = 0.f, hs2 = 0.f;
#pragma unroll
        for (int m = 0; m < 4; ++m) {
            int o = l + 32 * m;
            float h = hsc * u2v[m];
            hvv[m] = h;
            if (o < 100) { hs += h; hs2 += h * h; }
        }
        hs = wsum32(hs); hs2 = wsum32(hs2);
        float mu = hs * 0.01f;
        float var = hs2 * 0.01f - mu * mu;
        float inv = rsqrtf(var + 1e-5f);
#pragma unroll
        for (int m = 0; m < 4; ++m) {
            int o = l + 32 * m;
            if (o < 100) out[(size_t)gr * 100 + o] = (hvv[m] - mu) * inv * lng[o] + lnb[o];
        }
    }
}

extern "C" void kernel_launch(void* const* d_in, const int* in_sizes, int n_in,
                              void* d_out, int out_size) {
    const float* dst_h = (const float*)d_in[0];
    const float* neigh = (const float*)d_in[1];
    const float* edgef = (const float*)d_in[2];
    const float* dtp   = (const float*)d_in[3];
    const int*   edst  = (const int*)d_in[4];
    const float* Wq = (const float*)d_in[5];
    const float* bq = (const float*)d_in[6];
    const float* Wk = (const float*)d_in[7];
    const float* bk = (const float*)d_in[8];
    const float* Wv = (const float*)d_in[9];
    const float* bv = (const float*)d_in[10];
    const float* Wo = (const float*)d_in[11];
    const float* bo = (const float*)d_in[12];
    const float* tw = (const float*)d_in[13];
    const float* tb = (const float*)d_in[14];
    const float* lng = (const float*)d_in[15];
    const float* lnb = (const float*)d_in[16];
    float* out = (float*)d_out;
    int D = in_sizes[0] / D_NODE;
    int E = in_sizes[3];

    size_t smem1 = (200 * 133 + 32 * 200) * sizeof(float);   // 132000
    size_t smem2 = (TE * XPAD + KC * 132) * sizeof(float);   // 162752
    cudaFuncSetAttribute(k1_dst,  cudaFuncAttributeMaxDynamicSharedMemorySize, (int)smem1);
    cudaFuncSetAttribute(k5_final, cudaFuncAttributeMaxDynamicSharedMemorySize, (int)smem1);
    cudaFuncSetAttribute(k2_edge, cudaFuncAttributeMaxDynamicSharedMemorySize, (int)smem2);

    k_init<<<2048, 256>>>(bq, bk, bv, bo, tb, D);
    k1_dst<<<(D + 31) / 32, 256, smem1>>>(dst_h, Wq, D);
    k2_edge<<<(E + TE - 1) / TE, 256, smem2>>>(neigh, edgef, dtp, edst, Wk, Wv, tw, tb, E);
    k3_exp<<<(E + 255) / 256, 256>>>(edst, E);
    k4_agg<<<(E + 7) / 8, 256>>>(edst, E);
    k5_final<<<(D + 31) / 32, 256, smem1>>>(Wo, lng, lnb, out, D);
}